// round 3
// baseline (speedup 1.0000x reference)
#include <cuda_runtime.h>

#define N_NODES 100000
#define N_EDGES 3200000

// Scratch (device globals — no allocation allowed)
__device__ float g_deg[N_NODES];
__device__ float g_dis[N_NODES];
__device__ float g_y1[N_NODES * 64];   // (emb@W1)*dis
__device__ float g_s1[N_NODES * 64];   // edge-sum of y1[src] into dst
__device__ float g_h [N_NODES * 64];   // relu(dis*(s1+y1)+b1)
__device__ float g_y2[N_NODES * 32];   // (h@W2)*dis
__device__ float g_s2[N_NODES * 32];
__device__ float g_z [N_NODES * 32];   // dis*(s2+y2)+b2

__device__ __forceinline__ void red_add_f4(float4* addr, float4 v) {
    asm volatile("red.global.add.v4.f32 [%0], {%1,%2,%3,%4};"
                 :: "l"(addr), "f"(v.x), "f"(v.y), "f"(v.z), "f"(v.w)
                 : "memory");
}

// ---------------------------------------------------------------------------
// init: deg = 1 (self loop), s1 = s2 = 0
// ---------------------------------------------------------------------------
__global__ void init_kernel() {
    int i = blockIdx.x * blockDim.x + threadIdx.x;
    float4 z4 = make_float4(0.f, 0.f, 0.f, 0.f);
    if (i < N_NODES) g_deg[i] = 1.0f;
    if (i < N_NODES * 16) reinterpret_cast<float4*>(g_s1)[i] = z4;
    if (i < N_NODES * 8)  reinterpret_cast<float4*>(g_s2)[i] = z4;
}

// ---------------------------------------------------------------------------
// degree count over dst, then dis = rsqrt(deg)
// ---------------------------------------------------------------------------
__global__ void deg_kernel(const int* __restrict__ ei) {
    int e = blockIdx.x * blockDim.x + threadIdx.x;
    if (e < N_EDGES) {
        int dst = ei[N_EDGES + e];
        atomicAdd(&g_deg[dst], 1.0f);
    }
}

__global__ void dis_kernel() {
    int i = blockIdx.x * blockDim.x + threadIdx.x;
    if (i < N_NODES) g_dis[i] = rsqrtf(g_deg[i]);
}

// ---------------------------------------------------------------------------
// y = (x @ W) * dis[row]     (IN=128,OUT=64 layer1 | IN=64,OUT=32 layer2)
// 256 threads, each thread computes 4 output columns for one node of a tile.
// ---------------------------------------------------------------------------
template <int IN, int OUT>
__global__ __launch_bounds__(256) void gemm_scale_kernel(const float* __restrict__ xarg,
                                                         const float* __restrict__ W) {
    constexpr int CG = OUT / 4;        // float4 column groups
    constexpr int NT = 256 / CG;       // nodes per tile (16 | 32)
    __shared__ float Ws[IN * OUT];
    __shared__ float xs[NT * IN];

    const float* x = (IN == 128) ? xarg : (const float*)g_h;
    float*       y = (OUT == 64) ? g_y1 : g_y2;

    int tid = threadIdx.x;
    for (int i = tid; i < IN * OUT / 4; i += 256)
        reinterpret_cast<float4*>(Ws)[i] = reinterpret_cast<const float4*>(W)[i];
    __syncthreads();

    int cg = tid % CG;
    int nl = tid / CG;
    const int ntiles = N_NODES / NT;   // exact: 100000 % 16 == 100000 % 32 == 0

    for (int tile = blockIdx.x; tile < ntiles; tile += gridDim.x) {
        int node0 = tile * NT;
        const float4* xsrc = reinterpret_cast<const float4*>(x + (size_t)node0 * IN);
        for (int i = tid; i < NT * IN / 4; i += 256)
            reinterpret_cast<float4*>(xs)[i] = xsrc[i];
        __syncthreads();

        float4 acc = make_float4(0.f, 0.f, 0.f, 0.f);
        const float* xrow = xs + nl * IN;
        const float4* Ws4 = reinterpret_cast<const float4*>(Ws);
        #pragma unroll 8
        for (int k = 0; k < IN; k++) {
            float  xv = xrow[k];
            float4 wv = Ws4[k * CG + cg];
            acc.x += xv * wv.x; acc.y += xv * wv.y;
            acc.z += xv * wv.z; acc.w += xv * wv.w;
        }
        int node = node0 + nl;
        float s = g_dis[node];
        acc.x *= s; acc.y *= s; acc.z *= s; acc.w *= s;
        reinterpret_cast<float4*>(y)[(size_t)node * CG + cg] = acc;
        __syncthreads();
    }
}

// ---------------------------------------------------------------------------
// scatter: s[dst] += y[src]   (C4 float4 per edge row: 16 | 8)
// ---------------------------------------------------------------------------
template <int C4>
__global__ void scatter_kernel(const int* __restrict__ ei) {
    const float* y = (C4 == 16) ? g_y1 : g_y2;
    float*       s = (C4 == 16) ? g_s1 : g_s2;
    unsigned int gid = blockIdx.x * blockDim.x + threadIdx.x;
    unsigned int e = gid / C4;
    int c = (int)(gid % C4);
    if (e >= N_EDGES) return;
    int src = ei[e];
    int dst = ei[N_EDGES + e];
    float4 v = reinterpret_cast<const float4*>(y)[(size_t)src * C4 + c];
    red_add_f4(reinterpret_cast<float4*>(s) + (size_t)dst * C4 + c, v);
}

// ---------------------------------------------------------------------------
// combine: out = [relu]( dis*(s+y) + b )
// ---------------------------------------------------------------------------
template <int OUT, bool RELU>
__global__ void combine_kernel(const float* __restrict__ b) {
    constexpr int CG = OUT / 4;
    const float* sarr = (OUT == 64) ? g_s1 : g_s2;
    const float* yarr = (OUT == 64) ? g_y1 : g_y2;
    float*       oarr = (OUT == 64) ? g_h  : g_z;

    int i = blockIdx.x * blockDim.x + threadIdx.x;
    if (i >= N_NODES * CG) return;
    int node = i / CG, cg = i % CG;
    float d = g_dis[node];
    float4 sv = reinterpret_cast<const float4*>(sarr)[i];
    float4 yv = reinterpret_cast<const float4*>(yarr)[i];
    float4 bv = reinterpret_cast<const float4*>(b)[cg];
    float4 r;
    r.x = fmaf(d, sv.x + yv.x, bv.x);
    r.y = fmaf(d, sv.y + yv.y, bv.y);
    r.z = fmaf(d, sv.z + yv.z, bv.z);
    r.w = fmaf(d, sv.w + yv.w, bv.w);
    if (RELU) {
        r.x = fmaxf(r.x, 0.f); r.y = fmaxf(r.y, 0.f);
        r.z = fmaxf(r.z, 0.f); r.w = fmaxf(r.w, 0.f);
    }
    reinterpret_cast<float4*>(oarr)[i] = r;
}

// ---------------------------------------------------------------------------
// decode: out[e] = sigmoid( dot(z[src], z[dst]) )   8 threads / edge
// ---------------------------------------------------------------------------
__global__ void decode_kernel(const int* __restrict__ ei, float* __restrict__ out) {
    unsigned int gid = blockIdx.x * blockDim.x + threadIdx.x;
    unsigned int e = gid >> 3;
    int c = (int)(gid & 7);
    if (e >= N_EDGES) return;
    int src = ei[e];
    int dst = ei[N_EDGES + e];
    const float4* z4 = reinterpret_cast<const float4*>(g_z);
    float4 a = z4[(size_t)src * 8 + c];
    float4 b = z4[(size_t)dst * 8 + c];
    float p = a.x * b.x + a.y * b.y + a.z * b.z + a.w * b.w;
    p += __shfl_xor_sync(0xffffffffu, p, 1);
    p += __shfl_xor_sync(0xffffffffu, p, 2);
    p += __shfl_xor_sync(0xffffffffu, p, 4);
    if (c == 0) out[e] = 1.0f / (1.0f + expf(-p));
}

// ---------------------------------------------------------------------------
extern "C" void kernel_launch(void* const* d_in, const int* in_sizes, int n_in,
                              void* d_out, int out_size) {
    const float* emb = (const float*)d_in[0];
    const float* W1  = (const float*)d_in[1];
    const float* b1  = (const float*)d_in[2];
    const float* W2  = (const float*)d_in[3];
    const float* b2  = (const float*)d_in[4];
    const int*   ei  = (const int*)d_in[5];
    float*       out = (float*)d_out;

    init_kernel<<<(N_NODES * 16 + 255) / 256, 256>>>();
    deg_kernel<<<(N_EDGES + 255) / 256, 256>>>(ei);
    dis_kernel<<<(N_NODES + 255) / 256, 256>>>();

    // layer 1
    gemm_scale_kernel<128, 64><<<740, 256>>>(emb, W1);
    scatter_kernel<16><<<(N_EDGES * 16 + 255) / 256, 256>>>(ei);
    combine_kernel<64, true><<<(N_NODES * 16 + 255) / 256, 256>>>(b1);

    // layer 2
    gemm_scale_kernel<64, 32><<<1184, 256>>>(nullptr, W2);
    scatter_kernel<8><<<(N_EDGES * 8 + 255) / 256, 256>>>(ei);
    combine_kernel<32, false><<<(N_NODES * 8 + 255) / 256, 256>>>(b2);

    // decode
    decode_kernel<<<(N_EDGES * 8 + 255) / 256, 256>>>(ei, out);
}

// round 7
// speedup vs baseline: 1.7181x; 1.7181x over previous
#include <cuda_runtime.h>

#define N_NODES 100000
#define N_EDGES 3200000

// Scratch (device globals — no allocation allowed)
__device__ float g_deg[N_NODES];
__device__ float g_dis[N_NODES];
__device__ __align__(16) float g_y1[N_NODES * 64];   // (emb@W1)*dis
__device__ __align__(16) float g_s1[N_NODES * 64];   // edge-sum of y1[src] into dst
__device__ __align__(16) float g_y2[N_NODES * 32];   // (h@W2)*dis
__device__ __align__(16) float g_s2[N_NODES * 32];
__device__ __align__(16) float g_z [N_NODES * 32];   // dis*(s2+y2)+b2

__device__ __forceinline__ void red_add_f4(float4* addr, float4 v) {
    asm volatile("red.global.add.v4.f32 [%0], {%1,%2,%3,%4};"
                 :: "l"(addr), "f"(v.x), "f"(v.y), "f"(v.z), "f"(v.w)
                 : "memory");
}

// ---------------------------------------------------------------------------
// init: deg = 1 (self loop), s1 = s2 = 0
// ---------------------------------------------------------------------------
__global__ void init_kernel() {
    int i = blockIdx.x * blockDim.x + threadIdx.x;
    float4 z4 = make_float4(0.f, 0.f, 0.f, 0.f);
    if (i < N_NODES) g_deg[i] = 1.0f;
    if (i < N_NODES * 16) reinterpret_cast<float4*>(g_s1)[i] = z4;
    if (i < N_NODES * 8)  reinterpret_cast<float4*>(g_s2)[i] = z4;
}

__global__ void deg_kernel(const int* __restrict__ ei) {
    int e = blockIdx.x * blockDim.x + threadIdx.x;
    if (e < N_EDGES) atomicAdd(&g_deg[ei[N_EDGES + e]], 1.0f);
}

__global__ void dis_kernel() {
    int i = blockIdx.x * blockDim.x + threadIdx.x;
    if (i < N_NODES) g_dis[i] = rsqrtf(g_deg[i]);
}

// ---------------------------------------------------------------------------
// GEMM layer 1: y1 = (emb @ W1) * dis      [100000 x 128] @ [128 x 64]
// block tile: 256 nodes x 64 cols, k-block 32, thread tile 8x8.
// ---------------------------------------------------------------------------
#define XS_STRIDE 260   // 256 nodes + pad (keeps float4 alignment, few conflicts)

__global__ __launch_bounds__(256, 2) void gemm1_kernel(const float* __restrict__ x,
                                                       const float* __restrict__ W) {
    __shared__ float xsT[32][XS_STRIDE];
    __shared__ float Ws[32][64];

    const int tid = threadIdx.x;
    const int node0 = blockIdx.x * 256;
    const int ng = tid >> 3;   // 0..31 -> nodes ng*8..+7
    const int cg = tid & 7;    // 0..7  -> cols  cg*8..+7

    float acc[8][8];
    #pragma unroll
    for (int i = 0; i < 8; i++)
        #pragma unroll
        for (int j = 0; j < 8; j++) acc[i][j] = 0.f;

    for (int kb = 0; kb < 128; kb += 32) {
        // stage x transposed: xsT[k][node]
        #pragma unroll
        for (int l = 0; l < 8; l++) {
            int idx  = tid + l * 256;          // 0..2047
            int node = idx >> 3;               // 0..255
            int kc   = idx & 7;                // 0..7 (float4 chunks of 32-k-block)
            int gn   = min(node0 + node, N_NODES - 1);
            float4 v = reinterpret_cast<const float4*>(x)[(size_t)gn * 32 + (kb >> 2) + kc];
            xsT[kc * 4 + 0][node] = v.x;
            xsT[kc * 4 + 1][node] = v.y;
            xsT[kc * 4 + 2][node] = v.z;
            xsT[kc * 4 + 3][node] = v.w;
        }
        // stage W block [32 x 64]
        #pragma unroll
        for (int l = 0; l < 2; l++) {
            int idx = tid + l * 256;           // 0..511
            int k = idx >> 4, c4 = idx & 15;
            reinterpret_cast<float4*>(&Ws[k][0])[c4] =
                reinterpret_cast<const float4*>(W)[(size_t)(kb + k) * 16 + c4];
        }
        __syncthreads();

        #pragma unroll 4
        for (int k = 0; k < 32; k++) {
            float4 a0 = *reinterpret_cast<const float4*>(&xsT[k][ng * 8]);
            float4 a1 = *reinterpret_cast<const float4*>(&xsT[k][ng * 8 + 4]);
            float4 w0 = *reinterpret_cast<const float4*>(&Ws[k][cg * 8]);
            float4 w1 = *reinterpret_cast<const float4*>(&Ws[k][cg * 8 + 4]);
            float xv[8] = {a0.x, a0.y, a0.z, a0.w, a1.x, a1.y, a1.z, a1.w};
            float wv[8] = {w0.x, w0.y, w0.z, w0.w, w1.x, w1.y, w1.z, w1.w};
            #pragma unroll
            for (int i = 0; i < 8; i++)
                #pragma unroll
                for (int j = 0; j < 8; j++)
                    acc[i][j] = fmaf(xv[i], wv[j], acc[i][j]);
        }
        __syncthreads();
    }

    #pragma unroll
    for (int i = 0; i < 8; i++) {
        int node = node0 + ng * 8 + i;
        if (node < N_NODES) {
            float s = g_dis[node];
            float4 r0 = make_float4(acc[i][0]*s, acc[i][1]*s, acc[i][2]*s, acc[i][3]*s);
            float4 r1 = make_float4(acc[i][4]*s, acc[i][5]*s, acc[i][6]*s, acc[i][7]*s);
            float4* yrow = reinterpret_cast<float4*>(g_y1 + (size_t)node * 64 + cg * 8);
            yrow[0] = r0;
            yrow[1] = r1;
        }
    }
}

// ---------------------------------------------------------------------------
// GEMM layer 2 with fused combine1:
//   h = relu(dis*(s1+y1)+b1) computed in the loader; y2 = (h @ W2) * dis
// block tile: 256 nodes x 32 cols, k-block 32 (2 blocks), thread tile 8x4.
// ---------------------------------------------------------------------------
__global__ __launch_bounds__(256, 2) void gemm2_kernel(const float* __restrict__ W,
                                                       const float* __restrict__ b1) {
    __shared__ float xsT[32][XS_STRIDE];
    __shared__ float Ws[32][32];

    const int tid = threadIdx.x;
    const int node0 = blockIdx.x * 256;
    const int ng = tid >> 3;   // 0..31 -> nodes ng*8..+7
    const int cg = tid & 7;    // 0..7  -> cols  cg*4..+3

    float acc[8][4];
    #pragma unroll
    for (int i = 0; i < 8; i++)
        #pragma unroll
        for (int j = 0; j < 4; j++) acc[i][j] = 0.f;

    for (int kb = 0; kb < 64; kb += 32) {
        // stage h transposed, computing h = relu(dis*(s1+y1)+b1) on the fly
        #pragma unroll
        for (int l = 0; l < 8; l++) {
            int idx  = tid + l * 256;
            int node = idx >> 3;
            int kc   = idx & 7;
            int gn   = min(node0 + node, N_NODES - 1);
            size_t f4 = (size_t)gn * 16 + (kb >> 2) + kc;
            float4 sv = reinterpret_cast<const float4*>(g_s1)[f4];
            float4 yv = reinterpret_cast<const float4*>(g_y1)[f4];
            float4 bv = reinterpret_cast<const float4*>(b1)[(kb >> 2) + kc];
            float  d  = g_dis[gn];
            xsT[kc * 4 + 0][node] = fmaxf(fmaf(d, sv.x + yv.x, bv.x), 0.f);
            xsT[kc * 4 + 1][node] = fmaxf(fmaf(d, sv.y + yv.y, bv.y), 0.f);
            xsT[kc * 4 + 2][node] = fmaxf(fmaf(d, sv.z + yv.z, bv.z), 0.f);
            xsT[kc * 4 + 3][node] = fmaxf(fmaf(d, sv.w + yv.w, bv.w), 0.f);
        }
        // stage W block [32 x 32] = 256 float4, 1 per thread
        {
            int k = tid >> 3, c4 = tid & 7;
            reinterpret_cast<float4*>(&Ws[k][0])[c4] =
                reinterpret_cast<const float4*>(W)[(size_t)(kb + k) * 8 + c4];
        }
        __syncthreads();

        #pragma unroll 4
        for (int k = 0; k < 32; k++) {
            float4 a0 = *reinterpret_cast<const float4*>(&xsT[k][ng * 8]);
            float4 a1 = *reinterpret_cast<const float4*>(&xsT[k][ng * 8 + 4]);
            float4 w0 = *reinterpret_cast<const float4*>(&Ws[k][cg * 4]);
            float xv[8] = {a0.x, a0.y, a0.z, a0.w, a1.x, a1.y, a1.z, a1.w};
            float wv[4] = {w0.x, w0.y, w0.z, w0.w};
            #pragma unroll
            for (int i = 0; i < 8; i++)
                #pragma unroll
                for (int j = 0; j < 4; j++)
                    acc[i][j] = fmaf(xv[i], wv[j], acc[i][j]);
        }
        __syncthreads();
    }

    #pragma unroll
    for (int i = 0; i < 8; i++) {
        int node = node0 + ng * 8 + i;
        if (node < N_NODES) {
            float s = g_dis[node];
            float4 r = make_float4(acc[i][0]*s, acc[i][1]*s, acc[i][2]*s, acc[i][3]*s);
            reinterpret_cast<float4*>(g_y2 + (size_t)node * 32 + cg * 4)[0] = r;
        }
    }
}

// ---------------------------------------------------------------------------
// scatter: s[dst] += y[src]   (C4 float4 per edge row: 16 | 8)
// ---------------------------------------------------------------------------
template <int C4>
__global__ void scatter_kernel(const int* __restrict__ ei) {
    const float* y = (C4 == 16) ? g_y1 : g_y2;
    float*       s = (C4 == 16) ? g_s1 : g_s2;
    unsigned int gid = blockIdx.x * blockDim.x + threadIdx.x;
    unsigned int e = gid / C4;
    int c = (int)(gid % C4);
    if (e >= N_EDGES) return;
    int src = ei[e];
    int dst = ei[N_EDGES + e];
    float4 v = reinterpret_cast<const float4*>(y)[(size_t)src * C4 + c];
    red_add_f4(reinterpret_cast<float4*>(s) + (size_t)dst * C4 + c, v);
}

// ---------------------------------------------------------------------------
// combine layer 2: z = dis*(s2+y2) + b2
// ---------------------------------------------------------------------------
__global__ void combine2_kernel(const float* __restrict__ b) {
    int i = blockIdx.x * blockDim.x + threadIdx.x;
    if (i >= N_NODES * 8) return;
    int node = i >> 3, cg = i & 7;
    float d = g_dis[node];
    float4 sv = reinterpret_cast<const float4*>(g_s2)[i];
    float4 yv = reinterpret_cast<const float4*>(g_y2)[i];
    float4 bv = reinterpret_cast<const float4*>(b)[cg];
    float4 r;
    r.x = fmaf(d, sv.x + yv.x, bv.x);
    r.y = fmaf(d, sv.y + yv.y, bv.y);
    r.z = fmaf(d, sv.z + yv.z, bv.z);
    r.w = fmaf(d, sv.w + yv.w, bv.w);
    reinterpret_cast<float4*>(g_z)[i] = r;
}

// ---------------------------------------------------------------------------
// decode: out[e] = sigmoid( dot(z[src], z[dst]) )   8 threads / edge
// ---------------------------------------------------------------------------
__global__ void decode_kernel(const int* __restrict__ ei, float* __restrict__ out) {
    unsigned int gid = blockIdx.x * blockDim.x + threadIdx.x;
    unsigned int e = gid >> 3;
    int c = (int)(gid & 7);
    if (e >= N_EDGES) return;
    int src = ei[e];
    int dst = ei[N_EDGES + e];
    const float4* z4 = reinterpret_cast<const float4*>(g_z);
    float4 a = z4[(size_t)src * 8 + c];
    float4 b = z4[(size_t)dst * 8 + c];
    float p = a.x * b.x + a.y * b.y + a.z * b.z + a.w * b.w;
    p += __shfl_xor_sync(0xffffffffu, p, 1);
    p += __shfl_xor_sync(0xffffffffu, p, 2);
    p += __shfl_xor_sync(0xffffffffu, p, 4);
    if (c == 0) out[e] = 1.0f / (1.0f + expf(-p));
}

// ---------------------------------------------------------------------------
extern "C" void kernel_launch(void* const* d_in, const int* in_sizes, int n_in,
                              void* d_out, int out_size) {
    const float* emb = (const float*)d_in[0];
    const float* W1  = (const float*)d_in[1];
    const float* b1  = (const float*)d_in[2];
    const float* W2  = (const float*)d_in[3];
    const float* b2  = (const float*)d_in[4];
    const int*   ei  = (const int*)d_in[5];
    float*       out = (float*)d_out;

    const int GEMM_GRID = (N_NODES + 255) / 256;  // 391

    init_kernel<<<(N_NODES * 16 + 255) / 256, 256>>>();
    deg_kernel<<<(N_EDGES + 255) / 256, 256>>>(ei);
    dis_kernel<<<(N_NODES + 255) / 256, 256>>>();

    // layer 1
    gemm1_kernel<<<GEMM_GRID, 256>>>(emb, W1);
    scatter_kernel<16><<<(N_EDGES * 16 + 255) / 256, 256>>>(ei);

    // layer 2 (combine1 fused into gemm2 loader)
    gemm2_kernel<<<GEMM_GRID, 256>>>(W2, b1);
    scatter_kernel<8><<<(N_EDGES * 8 + 255) / 256, 256>>>(ei);
    combine2_kernel<<<(N_NODES * 8 + 255) / 256, 256>>>(b2);

    // decode
    decode_kernel<<<(N_EDGES * 8 + 255) / 256, 256>>>(ei, out);
}